// round 7
// baseline (speedup 1.0000x reference)
#include <cuda_runtime.h>
#include <math_constants.h>

// Hausdorff loss: x,y (8, 4096, 3) fp32 -> scalar, ONE kernel launch.
// |q-t|^2 = |q|^2 + (|t|^2 - 2 q.t); min/max on squared values, sqrt at end.
//
// Decomposition (148 SMs = 4 * 37): work unit = (dir, b, target-chunk),
// 2*8*37 = 592 CTAs = exactly 4/SM, one wave. Each CTA scans all 4096 queries
// against its ~111-target chunk.
//
// Per-query mins merge via atomicMax on COMPLEMENTED float bits:
//   for s >= 0, min(bits) == ~max(~bits), identity = 0  ==> zero-initialized
//   __device__ scratch needs NO init kernel. The last-done CTA reduces,
//   writes the output, and restores scratch/counter to zero (so every graph
//   replay sees the same initial state).

#define NB 8
#define V  4096
#define TC 37                        // 2*8*37 = 592 CTAs = 148*4
#define NCTA (2 * NB * TC)
#define THREADS 256
#define NPASS (V / (2 * THREADS))    // 8 passes, 2 queries/thread/pass
#define TMAX 111                     // ceil(4096/37)

__device__ unsigned g_comp[2 * NB * V];   // zero-init == identity for max(~bits)
__device__ unsigned g_done;               // zero-init; restored to 0 each launch

__global__ void __launch_bounds__(THREADS)
hd_main_kernel(const float* __restrict__ X, const float* __restrict__ Y,
               float* __restrict__ out) {
    __shared__ float4 sT[TMAX];
    __shared__ float wmax[THREADS / 32];
    __shared__ int s_last;

    const int tc  = blockIdx.x;          // 0..36
    const int b   = blockIdx.y;
    const int dir = blockIdx.z;
    const float* __restrict__ Qp = (dir == 0 ? X : Y) + (size_t)b * V * 3;
    const float* __restrict__ Tp = (dir == 0 ? Y : X) + (size_t)b * V * 3;
    unsigned* __restrict__ slab = g_comp + ((size_t)dir * NB + b) * V;

    const int t0 = (tc * V) / TC;
    const int nt = ((tc + 1) * V) / TC - t0;   // 110 or 111
    const int tid = threadIdx.x;

    // Stage this chunk's targets: (x, y, z, |t|^2).
    if (tid < nt) {
        const int g = t0 + tid;
        const float tx = Tp[g * 3 + 0];
        const float ty = Tp[g * 3 + 1];
        const float tz = Tp[g * 3 + 2];
        sT[tid] = make_float4(tx, ty, tz, tx * tx + ty * ty + tz * tz);
    }
    __syncthreads();

    #pragma unroll 1
    for (int p = 0; p < NPASS; p++) {
        const int q0 = p * (2 * THREADS) + tid;
        const int q1 = q0 + THREADS;

        const float q0x = Qp[q0 * 3 + 0], q0y = Qp[q0 * 3 + 1], q0z = Qp[q0 * 3 + 2];
        const float q1x = Qp[q1 * 3 + 0], q1y = Qp[q1 * 3 + 1], q1z = Qp[q1 * 3 + 2];
        const float a0x = -2.0f * q0x, a0y = -2.0f * q0y, a0z = -2.0f * q0z;
        const float a1x = -2.0f * q1x, a1y = -2.0f * q1y, a1z = -2.0f * q1z;
        const float q2_0 = q0x * q0x + q0y * q0y + q0z * q0z;
        const float q2_1 = q1x * q1x + q1y * q1y + q1z * q1z;

        float m0 = CUDART_INF_F, m1 = CUDART_INF_F;

        #pragma unroll 4
        for (int j = 0; j < nt; j++) {
            const float4 t = sT[j];   // broadcast LDS.128
            const float v0 = fmaf(a0x, t.x, fmaf(a0y, t.y, fmaf(a0z, t.z, t.w)));
            const float v1 = fmaf(a1x, t.x, fmaf(a1y, t.y, fmaf(a1z, t.z, t.w)));
            m0 = fminf(m0, v0);
            m1 = fminf(m1, v1);
        }

        const float s0 = fmaxf(q2_0 + m0, 0.0f);
        const float s1 = fmaxf(q2_1 + m1, 0.0f);
        // min over chunks == ~(max over chunks of ~bits); identity 0.
        atomicMax(&slab[q0], ~__float_as_uint(s0));
        atomicMax(&slab[q1], ~__float_as_uint(s1));
    }

    // ---- last-CTA-done finalize + state restore ----
    __threadfence();
    __syncthreads();
    if (tid == 0) {
        const unsigned prev = atomicAdd(&g_done, 1u);
        s_last = (prev == NCTA - 1);
    }
    __syncthreads();
    if (!s_last) return;

    __threadfence();   // acquire: see all CTAs' atomics
    float s = 0.0f;
    #pragma unroll 1
    for (int bb = 0; bb < NB; bb++) {
        float m = 0.0f;
        // Two slabs per batch: dir=0 at bb, dir=1 at NB+bb. Reset while reading.
        #pragma unroll 4
        for (int i = tid; i < 2 * V; i += THREADS) {
            const int r = (i < V) ? bb : (NB + bb);
            unsigned* p = g_comp + (size_t)r * V + (i & (V - 1));
            m = fmaxf(m, __uint_as_float(~(*p)));
            *p = 0u;
        }
        #pragma unroll
        for (int off = 16; off > 0; off >>= 1)
            m = fmaxf(m, __shfl_xor_sync(0xffffffffu, m, off));
        if ((tid & 31) == 0) wmax[tid >> 5] = m;
        __syncthreads();
        if (tid == 0) {
            float mm = wmax[0];
            #pragma unroll
            for (int w = 1; w < THREADS / 32; w++) mm = fmaxf(mm, wmax[w]);
            s += sqrtf(mm);
        }
        __syncthreads();
    }
    if (tid == 0) {
        out[0] = s * (1.0f / (float)NB);   // LOSS_WEIGHT = 1.0
        g_done = 0u;                        // restore for next replay
    }
}

extern "C" void kernel_launch(void* const* d_in, const int* in_sizes, int n_in,
                              void* d_out, int out_size) {
    const float* x = (const float*)d_in[0];
    const float* y = (const float*)d_in[1];
    float* out = (float*)d_out;

    dim3 grid(TC, NB, 2);
    hd_main_kernel<<<grid, THREADS>>>(x, y, out);
}

// round 8
// speedup vs baseline: 1.6598x; 1.6598x over previous
#include <cuda_runtime.h>
#include <math_constants.h>

// Hausdorff loss: x,y (8, 4096, 3) fp32 -> scalar, TWO kernel launches.
// |q-t|^2 = |q|^2 + (|t|^2 - 2 q.t); min/max on squared values, sqrt at end.
//
// Decomposition (148 SMs = 4 * 37): work unit = (dir, b, target-chunk),
// 2*8*37 = 592 CTAs = exactly 4/SM, one wave. Each CTA scans all 4096 queries
// (4 per thread per pass, 4 passes) against its ~111-target smem chunk.
//
// Per-query mins merge via atomicMax on COMPLEMENTED float bits:
//   for s >= 0, min(bits) == ~max(~bits), identity = 0 ==> zero-initialized
//   __device__ scratch needs NO init kernel. The reduce kernel restores all
//   state to zero so every graph replay sees identical initial state.

#define NB 8
#define V  4096
#define TC 37                         // 2*8*37 = 592 CTAs = 148*4
#define THREADS 256
#define QPT 4                         // queries per thread per pass
#define NPASS (V / (QPT * THREADS))   // 4
#define TMAX 111                      // ceil(4096/37)

__device__ unsigned g_comp[2 * NB * V];  // zero-init == identity for max(~bits)
__device__ unsigned g_max[NB];           // zero-init; nonneg float bits, max
__device__ unsigned g_done;              // zero-init; reset by last reduce CTA

__global__ void __launch_bounds__(THREADS)
hd_main_kernel(const float* __restrict__ X, const float* __restrict__ Y) {
    __shared__ float4 sT[TMAX];

    const int tc  = blockIdx.x;          // 0..36
    const int b   = blockIdx.y;
    const int dir = blockIdx.z;
    const float* __restrict__ Qp = (dir == 0 ? X : Y) + (size_t)b * V * 3;
    const float* __restrict__ Tp = (dir == 0 ? Y : X) + (size_t)b * V * 3;
    unsigned* __restrict__ slab = g_comp + ((size_t)dir * NB + b) * V;

    const int t0 = (tc * V) / TC;
    const int nt = ((tc + 1) * V) / TC - t0;   // 110 or 111
    const int tid = threadIdx.x;

    // Stage this chunk's targets: (x, y, z, |t|^2).
    if (tid < nt) {
        const int g = t0 + tid;
        const float tx = Tp[g * 3 + 0];
        const float ty = Tp[g * 3 + 1];
        const float tz = Tp[g * 3 + 2];
        sT[tid] = make_float4(tx, ty, tz, tx * tx + ty * ty + tz * tz);
    }
    __syncthreads();

    #pragma unroll 1
    for (int p = 0; p < NPASS; p++) {
        const int qb = p * (QPT * THREADS) + tid;

        float ax[QPT], ay[QPT], az[QPT], q2[QPT], m[QPT];
        #pragma unroll
        for (int k = 0; k < QPT; k++) {
            const int q = qb + k * THREADS;
            const float qx = Qp[q * 3 + 0];
            const float qy = Qp[q * 3 + 1];
            const float qz = Qp[q * 3 + 2];
            ax[k] = -2.0f * qx; ay[k] = -2.0f * qy; az[k] = -2.0f * qz;
            q2[k] = qx * qx + qy * qy + qz * qz;
            m[k]  = CUDART_INF_F;
        }

        #pragma unroll 4
        for (int j = 0; j < nt; j++) {
            const float4 t = sT[j];   // broadcast LDS.128
            #pragma unroll
            for (int k = 0; k < QPT; k++) {
                const float v = fmaf(ax[k], t.x,
                                fmaf(ay[k], t.y,
                                fmaf(az[k], t.z, t.w)));
                m[k] = fminf(m[k], v);
            }
        }

        #pragma unroll
        for (int k = 0; k < QPT; k++) {
            const float s = fmaxf(q2[k] + m[k], 0.0f);
            // min over chunks == ~(max over chunks of ~bits); identity 0.
            atomicMax(&slab[qb + k * THREADS], ~__float_as_uint(s));
        }
    }
}

// 16 CTAs: CTA r reduces slab r (dir = r>>3, batch = r&7), restores it to 0,
// atomicMax into g_max[batch]. Last CTA computes the scalar and resets state.
__global__ void __launch_bounds__(THREADS)
hd_reduce_kernel(float* __restrict__ out) {
    __shared__ float wmax[THREADS / 32];
    __shared__ int s_last;
    const int r = blockIdx.x;
    unsigned* __restrict__ slab = g_comp + (size_t)r * V;
    const int tid = threadIdx.x;

    float m = 0.0f;
    #pragma unroll 4
    for (int i = tid; i < V; i += THREADS) {
        m = fmaxf(m, __uint_as_float(~slab[i]));
        slab[i] = 0u;                      // restore identity for next replay
    }

    #pragma unroll
    for (int off = 16; off > 0; off >>= 1)
        m = fmaxf(m, __shfl_xor_sync(0xffffffffu, m, off));
    if ((tid & 31) == 0) wmax[tid >> 5] = m;
    __syncthreads();

    if (tid == 0) {
        float mm = wmax[0];
        #pragma unroll
        for (int w = 1; w < THREADS / 32; w++) mm = fmaxf(mm, wmax[w]);
        atomicMax(&g_max[r & (NB - 1)], __float_as_uint(mm));  // nonneg bits
        __threadfence();
        const unsigned prev = atomicAdd(&g_done, 1u);
        s_last = (prev == 2 * NB - 1);
    }
    __syncthreads();
    if (!s_last) return;

    if (tid == 0) {
        __threadfence();   // acquire: see all CTAs' g_max updates
        float s = 0.0f;
        #pragma unroll
        for (int i = 0; i < NB; i++) {
            s += sqrtf(__uint_as_float(g_max[i]));
            g_max[i] = 0u;                 // restore
        }
        out[0] = s * (1.0f / (float)NB);   // LOSS_WEIGHT = 1.0
        g_done = 0u;                       // restore
    }
}

extern "C" void kernel_launch(void* const* d_in, const int* in_sizes, int n_in,
                              void* d_out, int out_size) {
    const float* x = (const float*)d_in[0];
    const float* y = (const float*)d_in[1];
    float* out = (float*)d_out;

    dim3 grid(TC, NB, 2);
    hd_main_kernel<<<grid, THREADS>>>(x, y);
    hd_reduce_kernel<<<2 * NB, THREADS>>>(out);
}

// round 9
// speedup vs baseline: 1.7323x; 1.0437x over previous
#include <cuda_runtime.h>
#include <math_constants.h>

// Hausdorff loss: x,y (8, 4096, 3) fp32 -> scalar, ONE kernel launch.
// |q-t|^2 = |q|^2 + (|t|^2 - 2 q.t); min/max on squared values, sqrt at end.
//
// Decomposition (148 SMs = 4 * 37): work unit = (dir, b, target-chunk),
// 2*8*37 = 592 CTAs = exactly 4/SM, one wave. Each CTA scans all 4096 queries
// (8 per thread per pass, 2 passes) against its ~111-target smem chunk.
//
// Per-query mins merge via atomicMax on COMPLEMENTED float bits:
//   for s >= 0, min(bits) == ~max(~bits), identity = 0 ==> zero-initialized
//   scratch needs NO init kernel.
// Per-slab last-done CTA reduces its own slab (parallel, overlapped tail);
// global last-done CTA emits the scalar. All state restored to zero each call.

#define NB 8
#define V  4096
#define TC 37                         // 2*8*37 = 592 CTAs = 148*4
#define THREADS 256
#define QPT 8                         // queries per thread per pass
#define NPASS (V / (QPT * THREADS))   // 2
#define TMAX 111                      // ceil(4096/37)
#define NSLAB (2 * NB)                // 16

__device__ unsigned g_comp[NSLAB * V];    // zero-init == identity for max(~bits)
__device__ unsigned g_max[NB];            // zero-init; nonneg float bits
__device__ unsigned g_slab_done[NSLAB];   // zero-init; restored each call
__device__ unsigned g_done;               // zero-init; restored each call

__global__ void __launch_bounds__(THREADS, 4)
hd_main_kernel(const float* __restrict__ X, const float* __restrict__ Y,
               float* __restrict__ out) {
    __shared__ float4 sT[TMAX];
    __shared__ float wmax[THREADS / 32];
    __shared__ int s_role;   // 0 = plain, 1 = slab reducer

    const int tc  = blockIdx.x;          // 0..36
    const int b   = blockIdx.y;
    const int dir = blockIdx.z;
    const int slab_id = dir * NB + b;
    const float* __restrict__ Qp = (dir == 0 ? X : Y) + (size_t)b * V * 3;
    const float* __restrict__ Tp = (dir == 0 ? Y : X) + (size_t)b * V * 3;
    unsigned* __restrict__ slab = g_comp + (size_t)slab_id * V;

    const int t0 = (tc * V) / TC;
    const int nt = ((tc + 1) * V) / TC - t0;   // 110 or 111
    const int tid = threadIdx.x;

    // Stage this chunk's targets: (x, y, z, |t|^2).
    if (tid < nt) {
        const int g = t0 + tid;
        const float tx = Tp[g * 3 + 0];
        const float ty = Tp[g * 3 + 1];
        const float tz = Tp[g * 3 + 2];
        sT[tid] = make_float4(tx, ty, tz, tx * tx + ty * ty + tz * tz);
    }
    __syncthreads();

    #pragma unroll 1
    for (int p = 0; p < NPASS; p++) {
        const int qb = p * (QPT * THREADS) + tid;

        float ax[QPT], ay[QPT], az[QPT], m[QPT];
        #pragma unroll
        for (int k = 0; k < QPT; k++) {
            const int q = qb + k * THREADS;
            ax[k] = -2.0f * Qp[q * 3 + 0];
            ay[k] = -2.0f * Qp[q * 3 + 1];
            az[k] = -2.0f * Qp[q * 3 + 2];
            m[k]  = CUDART_INF_F;
        }

        #pragma unroll 4
        for (int j = 0; j < nt; j++) {
            const float4 t = sT[j];   // broadcast LDS.128
            #pragma unroll
            for (int k = 0; k < QPT; k++) {
                const float v = fmaf(ax[k], t.x,
                                fmaf(ay[k], t.y,
                                fmaf(az[k], t.z, t.w)));
                m[k] = fminf(m[k], v);
            }
        }

        #pragma unroll
        for (int k = 0; k < QPT; k++) {
            // |q|^2 = 0.25 * (ax^2 + ay^2 + az^2)  (recomputed; saves regs)
            const float q2 = 0.25f * fmaf(ax[k], ax[k],
                                     fmaf(ay[k], ay[k], az[k] * az[k]));
            const float s = fmaxf(q2 + m[k], 0.0f);
            // min over chunks == ~(max over chunks of ~bits); identity 0.
            atomicMax(&slab[qb + k * THREADS], ~__float_as_uint(s));
        }
    }

    // ---- per-slab last-done CTA reduces its slab ----
    __threadfence();
    __syncthreads();
    if (tid == 0)
        s_role = (atomicAdd(&g_slab_done[slab_id], 1u) == TC - 1);
    __syncthreads();
    if (!s_role) return;

    __threadfence();   // acquire: all 37 chunk CTAs' atomics visible

    float mm = 0.0f;
    {   // 4096 words, 256 threads, uint4-vectorized: 4 uint4 per thread.
        uint4* __restrict__ slab4 = reinterpret_cast<uint4*>(slab);
        #pragma unroll
        for (int i = tid; i < V / 4; i += THREADS) {
            const uint4 w = slab4[i];
            mm = fmaxf(mm, __uint_as_float(~w.x));
            mm = fmaxf(mm, __uint_as_float(~w.y));
            mm = fmaxf(mm, __uint_as_float(~w.z));
            mm = fmaxf(mm, __uint_as_float(~w.w));
            slab4[i] = make_uint4(0u, 0u, 0u, 0u);   // restore identity
        }
    }
    #pragma unroll
    for (int off = 16; off > 0; off >>= 1)
        mm = fmaxf(mm, __shfl_xor_sync(0xffffffffu, mm, off));
    if ((tid & 31) == 0) wmax[tid >> 5] = mm;
    __syncthreads();

    if (tid == 0) {
        float mx = wmax[0];
        #pragma unroll
        for (int w = 1; w < THREADS / 32; w++) mx = fmaxf(mx, wmax[w]);
        atomicMax(&g_max[b], __float_as_uint(mx));   // nonneg bits
        g_slab_done[slab_id] = 0u;                   // restore (all 37 arrived)

        __threadfence();
        if (atomicAdd(&g_done, 1u) == NSLAB - 1) {   // global last: finalize
            __threadfence();
            float s = 0.0f;
            #pragma unroll
            for (int i = 0; i < NB; i++) {
                s += sqrtf(__uint_as_float(g_max[i]));
                g_max[i] = 0u;                       // restore
            }
            out[0] = s * (1.0f / (float)NB);         // LOSS_WEIGHT = 1.0
            g_done = 0u;                             // restore
        }
    }
}

extern "C" void kernel_launch(void* const* d_in, const int* in_sizes, int n_in,
                              void* d_out, int out_size) {
    const float* x = (const float*)d_in[0];
    const float* y = (const float*)d_in[1];
    float* out = (float*)d_out;

    dim3 grid(TC, NB, 2);
    hd_main_kernel<<<grid, THREADS>>>(x, y, out);
}